// round 1
// baseline (speedup 1.0000x reference)
#include <cuda_runtime.h>
#include <math.h>

#define NB 8
#define CTC 1024
#define LL 1024
#define NHEADS 16
#define NGROUPS 8
#define BN_EPS 1e-5f

// -------- scratch (allocation-free rule: __device__ globals) --------
__device__ float g_k[NB * 512 * LL];      // 16 MB
__device__ float g_q[NB * 512 * LL];      // 16 MB
__device__ float g_v[NB * 1024 * LL];     // 32 MB
__device__ float g_x1[NB * 1024 * LL];    // 32 MB  (tokens + kqv)

struct P25 { const float* p[25]; };
// index map: 0 tokens; k:1..6 (w,b,gamma,beta,mean,var); q:7..12; v:13..18; f:19..24

// =====================================================================
// Kernel A: fused grouped-conv GEMMs for K,Q,V with BN folded.
// Per (n, g): X_g = tokens[n, g*128:(g+1)*128, :]  (K=128)
//   z==0: rows 0..63 -> k conv (cout 64/grp), rows 64..127 -> q conv
//   z==1: rows 0..127 -> v conv (cout 128/grp)
// Block: 128 rows x 128 cols, 256 threads, 8x8 micro.
// =====================================================================
__global__ __launch_bounds__(256) void qkv_kernel(P25 in) {
    const float* __restrict__ tokens = in.p[0];
    const int t = threadIdx.x;
    const int col0 = blockIdx.x * 128;
    const int n = blockIdx.y >> 3, g = blockIdx.y & 7;
    const int z = blockIdx.z;

    __shared__ float Xs[32][132];
    __shared__ float Wt[32][132];
    __shared__ const float* wrowS[128];
    __shared__ float scaleS[128];
    __shared__ float biasS[128];

    if (t < 128) {
        int r = t;
        const float *w, *b, *ga, *be, *me, *va;
        int co;
        if (z == 0) {
            int base = (r < 64) ? 1 : 7;
            w = in.p[base]; b = in.p[base + 1]; ga = in.p[base + 2];
            be = in.p[base + 3]; me = in.p[base + 4]; va = in.p[base + 5];
            co = g * 64 + (r & 63);
        } else {
            w = in.p[13]; b = in.p[14]; ga = in.p[15];
            be = in.p[16]; me = in.p[17]; va = in.p[18];
            co = g * 128 + r;
        }
        float inv = ga[co] / sqrtf(va[co] + BN_EPS);
        wrowS[r] = w + (size_t)co * 128;
        scaleS[r] = inv;
        biasS[r] = b[co] * inv + be[co] - me[co] * inv;
    }
    __syncthreads();

    float acc[8][8];
#pragma unroll
    for (int i = 0; i < 8; i++)
#pragma unroll
        for (int j = 0; j < 8; j++) acc[i][j] = 0.f;

    const int tx = t & 15, ty = t >> 4;

    for (int kc0 = 0; kc0 < 128; kc0 += 32) {
        {   // load X tile [32 k][128 c], coalesced
            int kk = t >> 3, c0 = (t & 7) * 16;
            const float* src = tokens + ((size_t)(n * 1024 + g * 128 + kc0 + kk)) * LL + col0 + c0;
#pragma unroll
            for (int u = 0; u < 4; u++)
                *(float4*)&Xs[kk][c0 + 4 * u] = *(const float4*)(src + 4 * u);
        }
        {   // load W tile transposed + BN-scaled
            int r = t >> 1, kk0 = (t & 1) * 16;
            const float* src = wrowS[r] + kc0 + kk0;
            float s = scaleS[r];
#pragma unroll
            for (int u = 0; u < 4; u++) {
                float4 v4 = *(const float4*)(src + 4 * u);
                Wt[kk0 + 4 * u + 0][r] = v4.x * s;
                Wt[kk0 + 4 * u + 1][r] = v4.y * s;
                Wt[kk0 + 4 * u + 2][r] = v4.z * s;
                Wt[kk0 + 4 * u + 3][r] = v4.w * s;
            }
        }
        __syncthreads();
#pragma unroll
        for (int kk = 0; kk < 32; kk++) {
            float a[8], bb[8];
            *(float4*)&a[0]  = *(float4*)&Wt[kk][ty * 8];
            *(float4*)&a[4]  = *(float4*)&Wt[kk][ty * 8 + 4];
            *(float4*)&bb[0] = *(float4*)&Xs[kk][tx * 8];
            *(float4*)&bb[4] = *(float4*)&Xs[kk][tx * 8 + 4];
#pragma unroll
            for (int i = 0; i < 8; i++)
#pragma unroll
                for (int j = 0; j < 8; j++)
                    acc[i][j] += a[i] * bb[j];
        }
        __syncthreads();
    }

#pragma unroll
    for (int i = 0; i < 8; i++) {
        int r = ty * 8 + i;
        float bias = biasS[r];
        float* dst;
        if (z == 0) {
            if (r < 64) dst = g_k + ((size_t)(n * 512 + g * 64 + r)) * LL;
            else        dst = g_q + ((size_t)(n * 512 + g * 64 + (r - 64))) * LL;
        } else {
            dst = g_v + ((size_t)(n * 1024 + g * 128 + r)) * LL;
        }
#pragma unroll
        for (int j = 0; j < 8; j++)
            dst[col0 + tx * 8 + j] = acc[i][j] + bias;
    }
}

// =====================================================================
// Kernel B: flash attention per (n, h, q-tile of 128).
// S[k][q] = (1/32) * sum_d K[d][k] Q[d][q]; online softmax over k;
// O[d][q] += V[d][k] P[k][q]; writes x1 = tokens + kqv.
// smem ~137 KB -> dynamic.
// =====================================================================
__global__ __launch_bounds__(256) void flash_kernel(const float* __restrict__ tokens) {
    extern __shared__ float sm[];
    float* Qs  = sm;              // [32][132]
    float* Ks  = sm + 4224;       // [32][132]
    float* Vt  = sm + 8448;       // [128][68]  (V transposed: [k][d])
    float* Ss  = sm + 17152;      // [128][132]
    float* mS  = sm + 34048;      // [128]
    float* lS  = sm + 34176;      // [128]
    float* alS = sm + 34304;      // [128]
    float* pm  = sm + 34432;      // [2][128]
    float* ps  = sm + 34688;      // [2][128]

    const int t = threadIdx.x;
    const int q0 = blockIdx.x * 128;
    const int n = blockIdx.y >> 4, h = blockIdx.y & 15;

    const float* Qg = g_q + ((size_t)(n * 512 + h * 32)) * LL;
    const float* Kg = g_k + ((size_t)(n * 512 + h * 32)) * LL;
    const float* Vg = g_v + ((size_t)(n * 1024 + h * 64)) * LL;

    {   // load Q tile once
        int d = t >> 3, c0 = (t & 7) * 16;
        const float* src = Qg + (size_t)d * LL + q0 + c0;
#pragma unroll
        for (int u = 0; u < 4; u++)
            *(float4*)&Qs[d * 132 + c0 + 4 * u] = *(const float4*)(src + 4 * u);
    }
    if (t < 128) { mS[t] = -1e30f; lS[t] = 0.f; }

    float O[8][4];
#pragma unroll
    for (int i = 0; i < 8; i++)
#pragma unroll
        for (int j = 0; j < 4; j++) O[i][j] = 0.f;

    const int tx = t & 15, ty = t >> 4;   // score phase: 8k x 8q micro
    const int cg = t & 31, rg = t >> 5;   // PV phase: 8d x 4q micro

    for (int kb = 0; kb < 8; kb++) {
        const int k0 = kb * 128;
        {   // load K tile
            int d = t >> 3, c0 = (t & 7) * 16;
            const float* src = Kg + (size_t)d * LL + k0 + c0;
#pragma unroll
            for (int u = 0; u < 4; u++)
                *(float4*)&Ks[d * 132 + c0 + 4 * u] = *(const float4*)(src + 4 * u);
        }
        {   // load V tile transposed
            int d = t >> 2, kk0 = (t & 3) * 32;
            const float* src = Vg + (size_t)d * LL + k0 + kk0;
#pragma unroll
            for (int u = 0; u < 8; u++) {
                float4 v4 = *(const float4*)(src + 4 * u);
                Vt[(kk0 + 4 * u + 0) * 68 + d] = v4.x;
                Vt[(kk0 + 4 * u + 1) * 68 + d] = v4.y;
                Vt[(kk0 + 4 * u + 2) * 68 + d] = v4.z;
                Vt[(kk0 + 4 * u + 3) * 68 + d] = v4.w;
            }
        }
        __syncthreads();
        {   // scores -> Ss (scaled by 1/sqrt(L)=1/32)
            float s[8][8];
#pragma unroll
            for (int i = 0; i < 8; i++)
#pragma unroll
                for (int j = 0; j < 8; j++) s[i][j] = 0.f;
#pragma unroll
            for (int d = 0; d < 32; d++) {
                float a[8], b[8];
                *(float4*)&a[0] = *(float4*)&Ks[d * 132 + ty * 8];
                *(float4*)&a[4] = *(float4*)&Ks[d * 132 + ty * 8 + 4];
                *(float4*)&b[0] = *(float4*)&Qs[d * 132 + tx * 8];
                *(float4*)&b[4] = *(float4*)&Qs[d * 132 + tx * 8 + 4];
#pragma unroll
                for (int i = 0; i < 8; i++)
#pragma unroll
                    for (int j = 0; j < 8; j++)
                        s[i][j] += a[i] * b[j];
            }
#pragma unroll
            for (int i = 0; i < 8; i++) {
#pragma unroll
                for (int j = 0; j < 8; j++) s[i][j] *= 0.03125f;
                *(float4*)&Ss[(ty * 8 + i) * 132 + tx * 8]     = *(float4*)&s[i][0];
                *(float4*)&Ss[(ty * 8 + i) * 132 + tx * 8 + 4] = *(float4*)&s[i][4];
            }
        }
        __syncthreads();
        {   // softmax pass 1: per-column partial max (2 threads / column)
            int q = t & 127, half = t >> 7;
            float mx = -1e30f;
            for (int k = half * 64; k < half * 64 + 64; k++)
                mx = fmaxf(mx, Ss[k * 132 + q]);
            pm[half * 128 + q] = mx;
        }
        __syncthreads();
        if (t < 128) {
            float mb = fmaxf(pm[t], pm[128 + t]);
            float mnew = fmaxf(mS[t], mb);
            alS[t] = __expf(mS[t] - mnew);
            mS[t] = mnew;
        }
        __syncthreads();
        {   // pass 2: exponentiate in place + partial sums
            int q = t & 127, half = t >> 7;
            float mnew = mS[q];
            float sum = 0.f;
            for (int k = half * 64; k < half * 64 + 64; k++) {
                float e = __expf(Ss[k * 132 + q] - mnew);
                Ss[k * 132 + q] = e;
                sum += e;
            }
            ps[half * 128 + q] = sum;
        }
        __syncthreads();
        if (t < 128)
            lS[t] = lS[t] * alS[t] + ps[t] + ps[128 + t];
        // lS read only in epilogue (after loop-end sync); alS/Ss final here
        {   // PV accumulate with online rescale
            float al[4];
#pragma unroll
            for (int j = 0; j < 4; j++) al[j] = alS[cg * 4 + j];
#pragma unroll
            for (int i = 0; i < 8; i++)
#pragma unroll
                for (int j = 0; j < 4; j++) O[i][j] *= al[j];
            for (int kk = 0; kk < 128; kk++) {
                float a[8], b[4];
                *(float4*)&a[0] = *(float4*)&Vt[kk * 68 + rg * 8];
                *(float4*)&a[4] = *(float4*)&Vt[kk * 68 + rg * 8 + 4];
                *(float4*)&b[0] = *(float4*)&Ss[kk * 132 + cg * 4];
#pragma unroll
                for (int i = 0; i < 8; i++)
#pragma unroll
                    for (int j = 0; j < 4; j++)
                        O[i][j] += a[i] * b[j];
            }
        }
        __syncthreads();
    }
    {   // epilogue: normalize, residual add, write x1
        float rl[4];
#pragma unroll
        for (int j = 0; j < 4; j++) rl[j] = 1.f / lS[cg * 4 + j];
#pragma unroll
        for (int i = 0; i < 8; i++) {
            int c = h * 64 + rg * 8 + i;
            size_t base = ((size_t)(n * 1024) + c) * LL + q0 + cg * 4;
#pragma unroll
            for (int j = 0; j < 4; j++)
                g_x1[base + j] = tokens[base + j] + O[i][j] * rl[j];
        }
    }
}

// =====================================================================
// Kernel C: FF conv (groups=1) GEMM + BN fold + bias + residual.
// out = x1 + (fW' @ x1 + fb'),  per n: [1024x1024] @ [1024x1024].
// =====================================================================
__global__ __launch_bounds__(256) void ff_kernel(P25 in, float* __restrict__ out) {
    const float* __restrict__ fw  = in.p[19];
    const float* __restrict__ fb  = in.p[20];
    const float* __restrict__ fga = in.p[21];
    const float* __restrict__ fbe = in.p[22];
    const float* __restrict__ fme = in.p[23];
    const float* __restrict__ fva = in.p[24];

    __shared__ float Xs[32][132];
    __shared__ float Wt[32][132];
    __shared__ float scaleS[128];
    __shared__ float biasS[128];

    const int t = threadIdx.x;
    const int l0 = blockIdx.x * 128, co0 = blockIdx.y * 128, n = blockIdx.z;

    if (t < 128) {
        int co = co0 + t;
        float inv = fga[co] / sqrtf(fva[co] + BN_EPS);
        scaleS[t] = inv;
        biasS[t] = fb[co] * inv + fbe[co] - fme[co] * inv;
    }
    __syncthreads();

    float acc[8][8];
#pragma unroll
    for (int i = 0; i < 8; i++)
#pragma unroll
        for (int j = 0; j < 8; j++) acc[i][j] = 0.f;

    const int tx = t & 15, ty = t >> 4;

    for (int kc0 = 0; kc0 < 1024; kc0 += 32) {
        {
            int kk = t >> 3, c0 = (t & 7) * 16;
            const float* src = g_x1 + ((size_t)(n * 1024 + kc0 + kk)) * LL + l0 + c0;
#pragma unroll
            for (int u = 0; u < 4; u++)
                *(float4*)&Xs[kk][c0 + 4 * u] = *(const float4*)(src + 4 * u);
        }
        {
            int r = t >> 1, kk0 = (t & 1) * 16;
            const float* src = fw + (size_t)(co0 + r) * 1024 + kc0 + kk0;
            float s = scaleS[r];
#pragma unroll
            for (int u = 0; u < 4; u++) {
                float4 v4 = *(const float4*)(src + 4 * u);
                Wt[kk0 + 4 * u + 0][r] = v4.x * s;
                Wt[kk0 + 4 * u + 1][r] = v4.y * s;
                Wt[kk0 + 4 * u + 2][r] = v4.z * s;
                Wt[kk0 + 4 * u + 3][r] = v4.w * s;
            }
        }
        __syncthreads();
#pragma unroll
        for (int kk = 0; kk < 32; kk++) {
            float a[8], bb[8];
            *(float4*)&a[0]  = *(float4*)&Wt[kk][ty * 8];
            *(float4*)&a[4]  = *(float4*)&Wt[kk][ty * 8 + 4];
            *(float4*)&bb[0] = *(float4*)&Xs[kk][tx * 8];
            *(float4*)&bb[4] = *(float4*)&Xs[kk][tx * 8 + 4];
#pragma unroll
            for (int i = 0; i < 8; i++)
#pragma unroll
                for (int j = 0; j < 8; j++)
                    acc[i][j] += a[i] * bb[j];
        }
        __syncthreads();
    }

#pragma unroll
    for (int i = 0; i < 8; i++) {
        int r = ty * 8 + i;
        size_t rowbase = ((size_t)(n * 1024 + co0 + r)) * LL + l0 + tx * 8;
        float bias = biasS[r];
#pragma unroll
        for (int j = 0; j < 8; j++)
            out[rowbase + j] = g_x1[rowbase + j] + acc[i][j] + bias;
    }
}

// =====================================================================
extern "C" void kernel_launch(void* const* d_in, const int* in_sizes, int n_in,
                              void* d_out, int out_size) {
    (void)in_sizes; (void)n_in; (void)out_size;
    P25 in;
    for (int i = 0; i < 25; i++) in.p[i] = (const float*)d_in[i];
    const float* tokens = (const float*)d_in[0];
    float* out = (float*)d_out;

    // flash kernel needs ~137 KB dynamic smem (idempotent host call; capture-safe)
    const int SMEM_B = 34944 * sizeof(float);
    cudaFuncSetAttribute(flash_kernel, cudaFuncAttributeMaxDynamicSharedMemorySize, SMEM_B);

    qkv_kernel<<<dim3(8, 64, 2), 256>>>(in);
    flash_kernel<<<dim3(8, 128), 256, SMEM_B>>>(tokens);
    ff_kernel<<<dim3(8, 8, 8), 256>>>(in, out);
}

// round 4
// speedup vs baseline: 1.2846x; 1.2846x over previous
#include <cuda_runtime.h>
#include <math.h>
#include <stdint.h>

#define NB 8
#define CTC 1024
#define LL 1024
#define BN_EPS 1e-5f

// -------- scratch (allocation-free rule: __device__ globals) --------
__device__ float g_k[NB * 512 * LL];
__device__ float g_q[NB * 512 * LL];
__device__ float g_v[NB * 1024 * LL];
__device__ float g_x1[NB * 1024 * LL];

struct P25 { const float* p[25]; };
// 0 tokens; k:1..6 (w,b,gamma,beta,mean,var); q:7..12; v:13..18; f:19..24

// ===================== generic helpers =====================
__device__ __forceinline__ uint32_t smem_u32(const void* p) {
    uint32_t a;
    asm("{ .reg .u64 t; cvta.to.shared.u64 t, %1; cvt.u32.u64 %0, t; }" : "=r"(a) : "l"(p));
    return a;
}
__device__ __forceinline__ uint32_t to_tf32(float f) {
    uint32_t r;
    asm("cvt.rna.tf32.f32 %0, %1;" : "=r"(r) : "f"(f));
    return r;
}
static __device__ __forceinline__ uint32_t sw128(uint32_t b) { return b ^ ((b >> 3) & 0x70); }

// ===================== tcgen05 helpers (sm_103a-only) =====================
#if defined(__CUDA_ARCH_FEAT_SM103_ALL) || !defined(__CUDA_ARCH__)
#define HAS_TCGEN05 1
#endif

#ifdef HAS_TCGEN05
__device__ __forceinline__ uint32_t elect_one() {
    uint32_t p;
    asm volatile("{ .reg .pred p; elect.sync _|p, 0xFFFFFFFF; selp.b32 %0, 1, 0, p; }" : "=r"(p));
    return p;
}
#define MBAR_INIT(a, c) asm volatile("mbarrier.init.shared.b64 [%0], %1;" :: "r"(a), "r"(c) : "memory")
#define MBAR_INVAL(a)   asm volatile("mbarrier.inval.shared.b64 [%0];" :: "r"(a) : "memory")
#define MBAR_WAIT(a, ph) do { \
    uint32_t _m = (a), _p = (ph), _d; \
    asm volatile("{ .reg .pred p; mbarrier.try_wait.parity.acquire.cta.shared::cta.b64 p, [%1], %2; selp.b32 %0,1,0,p; }" \
        : "=r"(_d) : "r"(_m), "r"(_p) : "memory"); \
    if (!_d) { \
        asm volatile("{ .reg .pred P1; WL_%=: mbarrier.try_wait.parity.acquire.cta.shared::cta.b64 P1, [%0], %1, 0x989680; @P1 bra.uni WD_%=; bra.uni WL_%=; WD_%=: }" \
            :: "r"(_m), "r"(_p) : "memory"); \
    } } while (0)

#define TC_ALLOC(sa, n)   asm volatile("tcgen05.alloc.cta_group::1.sync.aligned.shared::cta.b32 [%0], %1;" :: "r"(sa), "r"(n) : "memory")
#define TC_DEALLOC(t, n)  asm volatile("tcgen05.dealloc.cta_group::1.sync.aligned.b32 %0, %1;" :: "r"(t), "r"(n))
#define TC_COMMIT(mb)     asm volatile("tcgen05.commit.cta_group::1.mbarrier::arrive::one.shared::cluster.b64 [%0];" :: "r"(mb) : "memory")
#define TC_WAIT_LD()      asm volatile("tcgen05.wait::ld.sync.aligned;" ::: "memory")
#define TC_FENCE_AFTER()  asm volatile("tcgen05.fence::after_thread_sync;" ::: "memory")
#define TC_FENCE_BEFORE() asm volatile("tcgen05.fence::before_thread_sync;" ::: "memory")
#define FENCE_ASYNC()     asm volatile("fence.proxy.async.shared::cta;" ::: "memory")

__device__ __forceinline__ void mma_tf32(uint32_t d, uint64_t ad, uint64_t bd,
                                         uint32_t idesc, uint32_t en) {
    asm volatile(
        "{ .reg .pred p; setp.ne.u32 p, %5, 0;"
        "tcgen05.mma.cta_group::1.kind::tf32 [%0], %1, %2, %3, {%4,%4,%4,%4}, p; }"
        :: "r"(d), "l"(ad), "l"(bd), "r"(idesc), "r"(0u), "r"(en) : "memory");
}

#define LDTM_X32(r, a) \
    asm volatile("tcgen05.ld.sync.aligned.32x32b.x32.b32 " \
        "{%0,%1,%2,%3,%4,%5,%6,%7,%8,%9,%10,%11,%12,%13,%14,%15," \
        "%16,%17,%18,%19,%20,%21,%22,%23,%24,%25,%26,%27,%28,%29,%30,%31}, [%32];" \
        : "=r"((r)[0]),"=r"((r)[1]),"=r"((r)[2]),"=r"((r)[3]),"=r"((r)[4]),"=r"((r)[5]),"=r"((r)[6]),"=r"((r)[7]), \
          "=r"((r)[8]),"=r"((r)[9]),"=r"((r)[10]),"=r"((r)[11]),"=r"((r)[12]),"=r"((r)[13]),"=r"((r)[14]),"=r"((r)[15]), \
          "=r"((r)[16]),"=r"((r)[17]),"=r"((r)[18]),"=r"((r)[19]),"=r"((r)[20]),"=r"((r)[21]),"=r"((r)[22]),"=r"((r)[23]), \
          "=r"((r)[24]),"=r"((r)[25]),"=r"((r)[26]),"=r"((r)[27]),"=r"((r)[28]),"=r"((r)[29]),"=r"((r)[30]),"=r"((r)[31]) \
        : "r"(a))

static constexpr uint64_t DESC_SW128 =
    (uint64_t(2) << 61) | (uint64_t(1) << 46) | (uint64_t(64) << 32) | (uint64_t(1) << 16);
__device__ __forceinline__ uint64_t mk_desc(uint32_t addr) {
    return DESC_SW128 | ((uint64_t)(addr >> 4) & 0x3FFF);
}
// idesc kind::tf32 cg1: dtype F32, atype/btype TF32(2), N=128, M=128
#define TF32_IDESC ((1u << 4) | (2u << 7) | (2u << 10) | (16u << 17) | (8u << 24))
#endif // HAS_TCGEN05

// =====================================================================
// Kernel A: fused grouped-conv GEMMs for K,Q,V (SIMT)
// =====================================================================
__global__ __launch_bounds__(256) void qkv_kernel(P25 in) {
    const float* __restrict__ tokens = in.p[0];
    const int t = threadIdx.x;
    const int col0 = blockIdx.x * 128;
    const int n = blockIdx.y >> 3, g = blockIdx.y & 7;
    const int z = blockIdx.z;

    __shared__ float Xs[32][132];
    __shared__ float Wt[32][132];
    __shared__ const float* wrowS[128];
    __shared__ float scaleS[128];
    __shared__ float biasS[128];

    if (t < 128) {
        int r = t;
        const float *w, *b, *ga, *be, *me, *va;
        int co;
        if (z == 0) {
            int base = (r < 64) ? 1 : 7;
            w = in.p[base]; b = in.p[base + 1]; ga = in.p[base + 2];
            be = in.p[base + 3]; me = in.p[base + 4]; va = in.p[base + 5];
            co = g * 64 + (r & 63);
        } else {
            w = in.p[13]; b = in.p[14]; ga = in.p[15];
            be = in.p[16]; me = in.p[17]; va = in.p[18];
            co = g * 128 + r;
        }
        float inv = ga[co] / sqrtf(va[co] + BN_EPS);
        wrowS[r] = w + (size_t)co * 128;
        scaleS[r] = inv;
        biasS[r] = b[co] * inv + be[co] - me[co] * inv;
    }
    __syncthreads();

    float acc[8][8];
#pragma unroll
    for (int i = 0; i < 8; i++)
#pragma unroll
        for (int j = 0; j < 8; j++) acc[i][j] = 0.f;

    const int tx = t & 15, ty = t >> 4;

    for (int kc0 = 0; kc0 < 128; kc0 += 32) {
        {
            int kk = t >> 3, c0 = (t & 7) * 16;
            const float* src = tokens + ((size_t)(n * 1024 + g * 128 + kc0 + kk)) * LL + col0 + c0;
#pragma unroll
            for (int u = 0; u < 4; u++)
                *(float4*)&Xs[kk][c0 + 4 * u] = *(const float4*)(src + 4 * u);
        }
        {
            int r = t >> 1, kk0 = (t & 1) * 16;
            const float* src = wrowS[r] + kc0 + kk0;
            float s = scaleS[r];
#pragma unroll
            for (int u = 0; u < 4; u++) {
                float4 v4 = *(const float4*)(src + 4 * u);
                Wt[kk0 + 4 * u + 0][r] = v4.x * s;
                Wt[kk0 + 4 * u + 1][r] = v4.y * s;
                Wt[kk0 + 4 * u + 2][r] = v4.z * s;
                Wt[kk0 + 4 * u + 3][r] = v4.w * s;
            }
        }
        __syncthreads();
#pragma unroll
        for (int kk = 0; kk < 32; kk++) {
            float a[8], bb[8];
            *(float4*)&a[0]  = *(float4*)&Wt[kk][ty * 8];
            *(float4*)&a[4]  = *(float4*)&Wt[kk][ty * 8 + 4];
            *(float4*)&bb[0] = *(float4*)&Xs[kk][tx * 8];
            *(float4*)&bb[4] = *(float4*)&Xs[kk][tx * 8 + 4];
#pragma unroll
            for (int i = 0; i < 8; i++)
#pragma unroll
                for (int j = 0; j < 8; j++)
                    acc[i][j] += a[i] * bb[j];
        }
        __syncthreads();
    }

#pragma unroll
    for (int i = 0; i < 8; i++) {
        int r = ty * 8 + i;
        float bias = biasS[r];
        float* dst;
        if (z == 0) {
            if (r < 64) dst = g_k + ((size_t)(n * 512 + g * 64 + r)) * LL;
            else        dst = g_q + ((size_t)(n * 512 + g * 64 + (r - 64))) * LL;
        } else {
            dst = g_v + ((size_t)(n * 1024 + g * 128 + r)) * LL;
        }
#pragma unroll
        for (int j = 0; j < 8; j++)
            dst[col0 + tx * 8 + j] = acc[i][j] + bias;
    }
}

// =====================================================================
// Kernel B: flash attention (SIMT)
// =====================================================================
__global__ __launch_bounds__(256) void flash_kernel(const float* __restrict__ tokens) {
    extern __shared__ float sm[];
    float* Qs  = sm;
    float* Ks  = sm + 4224;
    float* Vt  = sm + 8448;
    float* Ss  = sm + 17152;
    float* mS  = sm + 34048;
    float* lS  = sm + 34176;
    float* alS = sm + 34304;
    float* pm  = sm + 34432;
    float* ps  = sm + 34688;

    const int t = threadIdx.x;
    const int q0 = blockIdx.x * 128;
    const int n = blockIdx.y >> 4, h = blockIdx.y & 15;

    const float* Qg = g_q + ((size_t)(n * 512 + h * 32)) * LL;
    const float* Kg = g_k + ((size_t)(n * 512 + h * 32)) * LL;
    const float* Vg = g_v + ((size_t)(n * 1024 + h * 64)) * LL;

    {
        int d = t >> 3, c0 = (t & 7) * 16;
        const float* src = Qg + (size_t)d * LL + q0 + c0;
#pragma unroll
        for (int u = 0; u < 4; u++)
            *(float4*)&Qs[d * 132 + c0 + 4 * u] = *(const float4*)(src + 4 * u);
    }
    if (t < 128) { mS[t] = -1e30f; lS[t] = 0.f; }

    float O[8][4];
#pragma unroll
    for (int i = 0; i < 8; i++)
#pragma unroll
        for (int j = 0; j < 4; j++) O[i][j] = 0.f;

    const int tx = t & 15, ty = t >> 4;
    const int cg = t & 31, rg = t >> 5;

    for (int kb = 0; kb < 8; kb++) {
        const int k0 = kb * 128;
        {
            int d = t >> 3, c0 = (t & 7) * 16;
            const float* src = Kg + (size_t)d * LL + k0 + c0;
#pragma unroll
            for (int u = 0; u < 4; u++)
                *(float4*)&Ks[d * 132 + c0 + 4 * u] = *(const float4*)(src + 4 * u);
        }
        {
            int d = t >> 2, kk0 = (t & 3) * 32;
            const float* src = Vg + (size_t)d * LL + k0 + kk0;
#pragma unroll
            for (int u = 0; u < 8; u++) {
                float4 v4 = *(const float4*)(src + 4 * u);
                Vt[(kk0 + 4 * u + 0) * 68 + d] = v4.x;
                Vt[(kk0 + 4 * u + 1) * 68 + d] = v4.y;
                Vt[(kk0 + 4 * u + 2) * 68 + d] = v4.z;
                Vt[(kk0 + 4 * u + 3) * 68 + d] = v4.w;
            }
        }
        __syncthreads();
        {
            float s[8][8];
#pragma unroll
            for (int i = 0; i < 8; i++)
#pragma unroll
                for (int j = 0; j < 8; j++) s[i][j] = 0.f;
#pragma unroll
            for (int d = 0; d < 32; d++) {
                float a[8], b[8];
                *(float4*)&a[0] = *(float4*)&Ks[d * 132 + ty * 8];
                *(float4*)&a[4] = *(float4*)&Ks[d * 132 + ty * 8 + 4];
                *(float4*)&b[0] = *(float4*)&Qs[d * 132 + tx * 8];
                *(float4*)&b[4] = *(float4*)&Qs[d * 132 + tx * 8 + 4];
#pragma unroll
                for (int i = 0; i < 8; i++)
#pragma unroll
                    for (int j = 0; j < 8; j++)
                        s[i][j] += a[i] * b[j];
            }
#pragma unroll
            for (int i = 0; i < 8; i++) {
#pragma unroll
                for (int j = 0; j < 8; j++) s[i][j] *= 0.03125f;
                *(float4*)&Ss[(ty * 8 + i) * 132 + tx * 8]     = *(float4*)&s[i][0];
                *(float4*)&Ss[(ty * 8 + i) * 132 + tx * 8 + 4] = *(float4*)&s[i][4];
            }
        }
        __syncthreads();
        {
            int q = t & 127, half = t >> 7;
            float mx = -1e30f;
            for (int k = half * 64; k < half * 64 + 64; k++)
                mx = fmaxf(mx, Ss[k * 132 + q]);
            pm[half * 128 + q] = mx;
        }
        __syncthreads();
        if (t < 128) {
            float mb = fmaxf(pm[t], pm[128 + t]);
            float mnew = fmaxf(mS[t], mb);
            alS[t] = __expf(mS[t] - mnew);
            mS[t] = mnew;
        }
        __syncthreads();
        {
            int q = t & 127, half = t >> 7;
            float mnew = mS[q];
            float sum = 0.f;
            for (int k = half * 64; k < half * 64 + 64; k++) {
                float e = __expf(Ss[k * 132 + q] - mnew);
                Ss[k * 132 + q] = e;
                sum += e;
            }
            ps[half * 128 + q] = sum;
        }
        __syncthreads();
        if (t < 128)
            lS[t] = lS[t] * alS[t] + ps[t] + ps[128 + t];
        {
            float al[4];
#pragma unroll
            for (int j = 0; j < 4; j++) al[j] = alS[cg * 4 + j];
#pragma unroll
            for (int i = 0; i < 8; i++)
#pragma unroll
                for (int j = 0; j < 4; j++) O[i][j] *= al[j];
            for (int kk = 0; kk < 128; kk++) {
                float a[8], b[4];
                *(float4*)&a[0] = *(float4*)&Vt[kk * 68 + rg * 8];
                *(float4*)&a[4] = *(float4*)&Vt[kk * 68 + rg * 8 + 4];
                *(float4*)&b[0] = *(float4*)&Ss[kk * 132 + cg * 4];
#pragma unroll
                for (int i = 0; i < 8; i++)
#pragma unroll
                    for (int j = 0; j < 4; j++)
                        O[i][j] += a[i] * b[j];
            }
        }
        __syncthreads();
    }
    {
        float rl[4];
#pragma unroll
        for (int j = 0; j < 4; j++) rl[j] = 1.f / lS[cg * 4 + j];
#pragma unroll
        for (int i = 0; i < 8; i++) {
            int c = h * 64 + rg * 8 + i;
            size_t base = ((size_t)(n * 1024) + c) * LL + q0 + cg * 4;
#pragma unroll
            for (int j = 0; j < 4; j++)
                g_x1[base + j] = tokens[base + j] + O[i][j] * rl[j];
        }
    }
}

// =====================================================================
// Kernel C: FF conv. tcgen05 kind::tf32 on sm_103a, SIMT fallback else.
// out = x1 + (W'_bn @ x1 + b'), per n a 1024x1024x1024 GEMM.
// =====================================================================
#define FF_SMEM 69632

__global__ __launch_bounds__(256) void ff_tc_kernel(P25 in, float* __restrict__ out) {
    extern __shared__ char smc[];
    float* scaleS = (float*)(smc + 64);
    float* biasS  = (float*)(smc + 576);

    const int t = threadIdx.x;
    const int l0 = blockIdx.x * 128, co0 = blockIdx.y * 128, n = blockIdx.z;

    if (t < 128) {
        int co = co0 + t;
        float inv = in.p[21][co] / sqrtf(in.p[24][co] + BN_EPS);
        scaleS[t] = inv;
        biasS[t] = in.p[20][co] * inv + in.p[22][co] - in.p[23][co] * inv;
    }

    const float* __restrict__ Wp = in.p[19];
    const float* __restrict__ Xp = g_x1 + (size_t)n * 1024 * 1024;

#if defined(__CUDA_ARCH_FEAT_SM103_ALL)
    // ---------------- tcgen05 tf32 path ----------------
    const uint32_t sb = smem_u32(smc);
    if (t < 32) TC_ALLOC(sb + 0, 128);
    if (t == 0) MBAR_INIT(sb + 8, 1);
    __syncthreads();

    uint32_t tmem;
    asm volatile("ld.shared.b32 %0, [%1];" : "=r"(tmem) : "r"(sb + 0));

    auto loadA = [&](int kc, int buf) {
        uint32_t ab = sb + 2048u + (uint32_t)buf * 32768u;
#pragma unroll
        for (int it = 0; it < 4; it++) {
            int id = t + it * 256;
            int r = id >> 3, kq = id & 7;
            float4 v = *(const float4*)(Wp + (size_t)(co0 + r) * 1024 + kc + kq * 4);
            float s = scaleS[r];
            uint32_t x0 = to_tf32(v.x * s), x1 = to_tf32(v.y * s);
            uint32_t x2 = to_tf32(v.z * s), x3 = to_tf32(v.w * s);
            uint32_t addr = ab + sw128((uint32_t)(r * 128 + kq * 16));
            asm volatile("st.shared.v4.b32 [%0], {%1,%2,%3,%4};"
                         :: "r"(addr), "r"(x0), "r"(x1), "r"(x2), "r"(x3) : "memory");
        }
    };
    auto loadB = [&](int kc, int buf) {
        uint32_t bb = sb + 2048u + 16384u + (uint32_t)buf * 32768u;
#pragma unroll
        for (int it = 0; it < 4; it++) {
            int id = t + it * 256;
            int l = id & 127, kq = id >> 7;
            const float* src = Xp + (size_t)(kc + kq * 4) * 1024 + l0 + l;
            uint32_t x0 = to_tf32(src[0]);
            uint32_t x1 = to_tf32(src[1024]);
            uint32_t x2 = to_tf32(src[2048]);
            uint32_t x3 = to_tf32(src[3072]);
            uint32_t addr = bb + sw128((uint32_t)(l * 128 + kq * 16));
            asm volatile("st.shared.v4.b32 [%0], {%1,%2,%3,%4};"
                         :: "r"(addr), "r"(x0), "r"(x1), "r"(x2), "r"(x3) : "memory");
        }
    };

    loadA(0, 0);
    loadB(0, 0);
    FENCE_ASYNC();
    __syncthreads();

    for (int c = 0; c < 32; c++) {
        int buf = c & 1;
        if (t < 32) {
            TC_FENCE_AFTER();
            if (elect_one()) {
                uint64_t ad = mk_desc(sb + 2048u + (uint32_t)buf * 32768u);
                uint64_t bd = mk_desc(sb + 2048u + 16384u + (uint32_t)buf * 32768u);
#pragma unroll
                for (int s = 0; s < 4; s++)
                    mma_tf32(tmem, ad + s * 2, bd + s * 2, TF32_IDESC,
                             (c > 0 || s > 0) ? 1u : 0u);
                TC_COMMIT(sb + 8);
            }
        }
        if (c + 1 < 32) {
            loadA((c + 1) * 32, buf ^ 1);
            loadB((c + 1) * 32, buf ^ 1);
            FENCE_ASYNC();
        }
        MBAR_WAIT(sb + 8, (uint32_t)(c & 1));
        __syncthreads();
    }

    TC_FENCE_AFTER();
    {
        int w = t >> 5, lane = t & 31;
        uint32_t toff = tmem + ((uint32_t)(w & 3) << 21) + (uint32_t)((w >> 2) * 64);
        uint32_t d[64];
        LDTM_X32(d, toff);
        LDTM_X32(d + 32, toff + 32);
        TC_WAIT_LD();
        TC_FENCE_BEFORE();

        float* stg = (float*)(smc + 2048);
        int r = (w & 3) * 32 + lane;
        int ch = (w >> 2) * 64;
#pragma unroll
        for (int i = 0; i < 16; i++) {
            float4 v;
            v.x = __uint_as_float(d[4 * i + 0]);
            v.y = __uint_as_float(d[4 * i + 1]);
            v.z = __uint_as_float(d[4 * i + 2]);
            v.w = __uint_as_float(d[4 * i + 3]);
            *(float4*)&stg[r * 132 + ch + 4 * i] = v;
        }
    }
    __syncthreads();
    {
        float* stg = (float*)(smc + 2048);
        int r = t >> 1, c0 = (t & 1) * 64;
        size_t gbase = ((size_t)(n * 1024 + co0 + r)) * 1024 + l0 + c0;
        float bias = biasS[r];
#pragma unroll
        for (int i = 0; i < 16; i++) {
            float4 v = *(float4*)&stg[r * 132 + c0 + 4 * i];
            float4 x = *(const float4*)(g_x1 + gbase + 4 * i);
            v.x += x.x + bias; v.y += x.y + bias;
            v.z += x.z + bias; v.w += x.w + bias;
            *(float4*)(out + gbase + 4 * i) = v;
        }
    }
    __syncthreads();
    if (t == 0) MBAR_INVAL(sb + 8);
    __syncthreads();
    if (t < 32) TC_DEALLOC(tmem, 128);
#else
    // ---------------- SIMT fallback (vanilla sm_103 PTX pass) ----------------
    float (*Xs)[132] = (float(*)[132])(smc + 2048);
    float (*Wt)[132] = (float(*)[132])(smc + 2048 + 16896);
    __syncthreads();

    float acc[8][8];
#pragma unroll
    for (int i = 0; i < 8; i++)
#pragma unroll
        for (int j = 0; j < 8; j++) acc[i][j] = 0.f;

    const int tx = t & 15, ty = t >> 4;

    for (int kc0 = 0; kc0 < 1024; kc0 += 32) {
        {
            int kk = t >> 3, c0 = (t & 7) * 16;
            const float* src = Xp + (size_t)(kc0 + kk) * LL + l0 + c0;
#pragma unroll
            for (int u = 0; u < 4; u++)
                *(float4*)&Xs[kk][c0 + 4 * u] = *(const float4*)(src + 4 * u);
        }
        {
            int r = t >> 1, kk0 = (t & 1) * 16;
            const float* src = Wp + (size_t)(co0 + r) * 1024 + kc0 + kk0;
            float s = scaleS[r];
#pragma unroll
            for (int u = 0; u < 4; u++) {
                float4 v4 = *(const float4*)(src + 4 * u);
                Wt[kk0 + 4 * u + 0][r] = v4.x * s;
                Wt[kk0 + 4 * u + 1][r] = v4.y * s;
                Wt[kk0 + 4 * u + 2][r] = v4.z * s;
                Wt[kk0 + 4 * u + 3][r] = v4.w * s;
            }
        }
        __syncthreads();
#pragma unroll
        for (int kk = 0; kk < 32; kk++) {
            float a[8], bb[8];
            *(float4*)&a[0]  = *(float4*)&Wt[kk][ty * 8];
            *(float4*)&a[4]  = *(float4*)&Wt[kk][ty * 8 + 4];
            *(float4*)&bb[0] = *(float4*)&Xs[kk][tx * 8];
            *(float4*)&bb[4] = *(float4*)&Xs[kk][tx * 8 + 4];
#pragma unroll
            for (int i = 0; i < 8; i++)
#pragma unroll
                for (int j = 0; j < 8; j++)
                    acc[i][j] += a[i] * bb[j];
        }
        __syncthreads();
    }

#pragma unroll
    for (int i = 0; i < 8; i++) {
        int r = ty * 8 + i;
        size_t rowbase = ((size_t)(n * 1024 + co0 + r)) * 1024 + l0 + tx * 8;
        float bias = biasS[r];
#pragma unroll
        for (int j = 0; j < 8; j++)
            out[rowbase + j] = g_x1[rowbase + j] + acc[i][j] + bias;
    }
#endif
}

// =====================================================================
extern "C" void kernel_launch(void* const* d_in, const int* in_sizes, int n_in,
                              void* d_out, int out_size) {
    (void)in_sizes; (void)n_in; (void)out_size;
    P25 in;
    for (int i = 0; i < 25; i++) in.p[i] = (const float*)d_in[i];
    const float* tokens = (const float*)d_in[0];
    float* out = (float*)d_out;

    const int SMEM_B = 34944 * sizeof(float);
    cudaFuncSetAttribute(flash_kernel, cudaFuncAttributeMaxDynamicSharedMemorySize, SMEM_B);
    cudaFuncSetAttribute(ff_tc_kernel, cudaFuncAttributeMaxDynamicSharedMemorySize, FF_SMEM);

    qkv_kernel<<<dim3(8, 64, 2), 256>>>(in);
    flash_kernel<<<dim3(8, 128), 256, SMEM_B>>>(tokens);
    ff_tc_kernel<<<dim3(8, 8, 8), 256, FF_SMEM>>>(in, out);
}